// round 2
// baseline (speedup 1.0000x reference)
#include <cuda_runtime.h>

#define BB 4
#define CC 32
#define HH 128
#define WW 240
#define JJ 15
#define HW (HH*WW)            // 30720
#define BHW (BB*HW)           // 122880
#define ROW 35                // 3 + C
#define WARP_FLOATS (32*ROW)  // 1120

// per-batch params: [0]=1/fx [1]=1/fy [2]=cx [3]=cy [4..15]=T(3x4) [16..27]=diff
__device__ float g_params[BB * 32];

__global__ void setup_params_kernel(const float* __restrict__ K,
                                    const float* __restrict__ M,
                                    const float* __restrict__ diff,
                                    const float* __restrict__ trans) {
    int b = threadIdx.x;
    if (b >= BB) return;
    const float* Kb = K + b * 9;
    float fxi = 1.0f / Kb[0];
    float fyi = 1.0f / Kb[4];
    float cx = Kb[2], cy = Kb[5];

    // Minv = [R^T, -R^T t; 0 1]
    const float* Mb = M + b * 16;
    float Minv[3][4];
    #pragma unroll
    for (int i = 0; i < 3; i++) {
        #pragma unroll
        for (int j = 0; j < 3; j++) Minv[i][j] = Mb[j * 4 + i];
        Minv[i][3] = -(Mb[0*4+i]*Mb[0*4+3] + Mb[1*4+i]*Mb[1*4+3] + Mb[2*4+i]*Mb[2*4+3]);
    }
    const float* Tr = trans + b * 16;
    float* P = g_params + b * 32;
    P[0] = fxi; P[1] = fyi; P[2] = cx; P[3] = cy;
    #pragma unroll
    for (int i = 0; i < 3; i++) {
        #pragma unroll
        for (int j = 0; j < 4; j++) {
            float s = 0.0f;
            #pragma unroll
            for (int k = 0; k < 3; k++) s += Tr[i*4+k] * Minv[k][j];
            if (j == 3) s += Tr[i*4+3];
            P[4 + i*4 + j] = s;
        }
    }
    #pragma unroll
    for (int i = 0; i < 12; i++) P[16 + i] = diff[b * 12 + i];
}

__global__ __launch_bounds__(128)
void get_3d_points_kernel(const float* __restrict__ depth_in,
                          const int*   __restrict__ mask_in,
                          const float* __restrict__ feat_in,
                          float*       __restrict__ out) {
    __shared__ float    s_pc[4 * WARP_FLOATS];  // 17.9 KB: 4 warps x 32 points x 35 floats
    __shared__ unsigned s_bits[128];            // 0.5 KB: 15-joint mask bitword per point

    const int tid  = threadIdx.x;
    const int lane = tid & 31;
    const int wrp  = tid >> 5;
    const int bp   = blockIdx.x * 128 + tid;    // grid = BHW/128 exactly
    const int b = bp / HW;
    const int p = bp - b * HW;
    const int hh = p / WW;
    const int ww = p - hh * WW;

    const float* P = g_params + b * 32;

    // pixel grid + K^-1
    float x  = (float)(ww + 71) * 4.0f;         // (w+71)*(1920/480)
    float y  = (float)hh * 8.4375f;             // h*(1080/128)
    float xb = (x - P[2]) * P[0];
    float yb = (y - P[3]) * P[1];

    float d0 = P[16], d1 = P[17], d2 = P[18], d3 = P[19];
    float d4 = P[20], d5 = P[21], d6 = P[22], d7 = P[23];
    float d8 = P[24], d9 = P[25], d10 = P[26], d11 = P[27];

    float xd = xb, yd = yb;
    #pragma unroll
    for (int it = 0; it < 5; it++) {
        float r2  = xd*xd + yd*yd;
        float num = 1.0f + ((d7*r2 + d6)*r2 + d5)*r2;
        float den = 1.0f + ((d4*r2 + d1)*r2 + d0)*r2;
        float ic  = num / den;
        float r4  = r2 * r2;
        float dX  = 2.0f*d2*xd*yd + d3*(r2 + 2.0f*xd*xd) + d8*r2 + d9*r4;
        float dY  = d2*(r2 + 2.0f*yd*yd) + 2.0f*d3*xd*yd + d10*r2 + d11*r4;
        xd = (xb - dX) * ic;
        yd = (yb - dY) * ic;
    }

    float dep = depth_in[bp];
    float X4 = xd * dep, Y4 = yd * dep;
    float px = P[4]*X4  + P[5]*Y4  + P[6]*dep  + P[7];
    float py = P[8]*X4  + P[9]*Y4  + P[10]*dep + P[11];
    float pz = P[12]*X4 + P[13]*Y4 + P[14]*dep + P[15];

    // stage this warp's 32 rows (stride 35 words -> conflict-free, gcd(35,32)=1)
    float* row = s_pc + wrp * WARP_FLOATS + lane * ROW;
    row[0] = px; row[1] = py; row[2] = pz;
    const float* fb = feat_in + (size_t)b * (CC * HW) + p;
    #pragma unroll
    for (int c = 0; c < CC; c++) row[3 + c] = fb[(size_t)c * HW];

    // pack the 15 per-joint masks for this point into one bitword
    unsigned mbits = 0;
    #pragma unroll
    for (int j = 0; j < JJ; j++)
        mbits |= ((unsigned)mask_in[(size_t)j * BHW + bp] & 1u) << j;
    s_bits[tid] = mbits;

    __syncwarp();

    // coalesced masked broadcast: chunks outer (index math hoisted), joints inner
    const float*    srcw = s_pc + wrp * WARP_FLOATS;
    const unsigned* bitw = s_bits + wrp * 32;
    float* outw = out + ((long)blockIdx.x * 128 + wrp * 32) * ROW;

    #pragma unroll
    for (int i = 0; i < 9; i++) {
        int chunk = i * 32 + lane;
        if (chunk < 280) {
            int s4  = chunk * 4;
            int q   = s4 / 35;             // local point 0..31
            int rem = s4 - q * 35;
            int bnd = 35 - rem;            // elems with idx < bnd belong to q

            float4 v = *(const float4*)(srcw + s4);
            unsigned b0 = bitw[q];
            unsigned b1 = (bnd < 4) ? bitw[q + 1] : b0;   // straddle only when bnd<4 (then q<=30)
            // per-component bit-word (bnd >= 1 always, so x uses b0)
            unsigned uy = (bnd > 1) ? b0 : b1;
            unsigned uz = (bnd > 2) ? b0 : b1;
            unsigned uw = (bnd > 3) ? b0 : b1;

            float* dp = outw + s4;
            #pragma unroll
            for (int j = 0; j < JJ; j++) {
                const unsigned bit = 1u << j;
                float4 o;
                o.x = (b0 & bit) ? v.x : 0.0f;
                o.y = (uy & bit) ? v.y : 0.0f;
                o.z = (uz & bit) ? v.z : 0.0f;
                o.w = (uw & bit) ? v.w : 0.0f;
                *(float4*)dp = o;
                dp += (long)BHW * ROW;
            }
        }
    }
}

extern "C" void kernel_launch(void* const* d_in, const int* in_sizes, int n_in,
                              void* d_out, int out_size) {
    const float* depth = (const float*)d_in[0];   // pred_depth [B,1,H,W]
    const int*   mask  = (const int*)  d_in[1];   // filter_mask [J,B,H,W] int32
    const float* K     = (const float*)d_in[2];   // [B,3,3]
    const float* M     = (const float*)d_in[3];   // [B,4,4]
    const float* diff  = (const float*)d_in[4];   // [B,12]
    const float* trans = (const float*)d_in[5];   // [B,4,4]
    const float* feat  = (const float*)d_in[6];   // [B,C,H,W]

    setup_params_kernel<<<1, 32>>>(K, M, diff, trans);
    get_3d_points_kernel<<<BHW / 128, 128>>>(depth, mask, feat, (float*)d_out);
}

// round 3
// speedup vs baseline: 1.0933x; 1.0933x over previous
#include <cuda_runtime.h>

#define BB 4
#define CC 32
#define HH 128
#define WW 240
#define JJ 15
#define HW (HH*WW)            // 30720
#define BHW (BB*HW)           // 122880
#define ROW 35                // 3 + C
#define PTS 128               // points per block
#define THREADS 480           // 15 warps: 4 compute, 15 store (1 per joint)

__global__ __launch_bounds__(THREADS)
void get_3d_points_kernel(const float* __restrict__ depth_in,
                          const int*   __restrict__ mask_in,
                          const float* __restrict__ feat_in,
                          const float* __restrict__ K_in,
                          const float* __restrict__ M_in,
                          const float* __restrict__ diff_in,
                          const float* __restrict__ trans_in,
                          float*       __restrict__ out) {
    __shared__ float    s_pc[PTS * ROW];   // 17.9 KB: 128 points x 35 floats
    __shared__ unsigned s_bits[PTS];       // 15-joint mask bitword per point

    const int tid = threadIdx.x;
    const int bp0 = blockIdx.x * PTS;      // block entirely within one batch (HW % 128 == 0)
    const int b   = bp0 / HW;

    // ---------------- Phase 1: warps 0-3 compute 128 points ----------------
    if (tid < PTS) {
        const int bp = bp0 + tid;
        const int p  = bp - b * HW;
        const int hh = p / WW;
        const int ww = p - hh * WW;

        // inline per-batch params (uniform per warp; hits L1/L2)
        const float* Kb = K_in + b * 9;
        const float fxi = 1.0f / Kb[0];
        const float fyi = 1.0f / Kb[4];
        const float cx = Kb[2], cy = Kb[5];

        // Minv = [R^T, -R^T t], T = trans * Minv (3x4)
        const float* Mb = M_in + b * 16;
        const float* Tr = trans_in + b * 16;
        float T[12];
        #pragma unroll
        for (int i = 0; i < 3; i++) {
            #pragma unroll
            for (int j = 0; j < 4; j++) {
                float s = (j == 3) ? Tr[i*4+3] : 0.0f;
                #pragma unroll
                for (int k = 0; k < 3; k++) {
                    float minv_kj = (j < 3) ? Mb[j*4+k]
                        : -(Mb[0*4+k]*Mb[0*4+3] + Mb[1*4+k]*Mb[1*4+3] + Mb[2*4+k]*Mb[2*4+3]);
                    s += Tr[i*4+k] * minv_kj;
                }
                T[i*4+j] = s;
            }
        }
        const float* D = diff_in + b * 12;
        float d0 = D[0], d1 = D[1], d2 = D[2], d3 = D[3];
        float d4 = D[4], d5 = D[5], d6 = D[6], d7 = D[7];
        float d8 = D[8], d9 = D[9], d10 = D[10], d11 = D[11];

        float x  = (float)(ww + 71) * 4.0f;     // (w+71)*(1920/480)
        float y  = (float)hh * 8.4375f;         // h*(1080/128)
        float xb = (x - cx) * fxi;
        float yb = (y - cy) * fyi;

        float xd = xb, yd = yb;
        #pragma unroll
        for (int it = 0; it < 5; it++) {
            float r2  = xd*xd + yd*yd;
            float num = 1.0f + ((d7*r2 + d6)*r2 + d5)*r2;
            float den = 1.0f + ((d4*r2 + d1)*r2 + d0)*r2;
            float ic  = num / den;
            float r4  = r2 * r2;
            float dX  = 2.0f*d2*xd*yd + d3*(r2 + 2.0f*xd*xd) + d8*r2 + d9*r4;
            float dY  = d2*(r2 + 2.0f*yd*yd) + 2.0f*d3*xd*yd + d10*r2 + d11*r4;
            xd = (xb - dX) * ic;
            yd = (yb - dY) * ic;
        }

        float dep = depth_in[bp];
        float X4 = xd * dep, Y4 = yd * dep;
        float* row = s_pc + tid * ROW;          // stride 35: conflict-free (gcd(35,32)=1)
        row[0] = T[0]*X4 + T[1]*Y4 + T[2]*dep  + T[3];
        row[1] = T[4]*X4 + T[5]*Y4 + T[6]*dep  + T[7];
        row[2] = T[8]*X4 + T[9]*Y4 + T[10]*dep + T[11];

        const float* fb = feat_in + (size_t)b * (CC * HW) + p;
        #pragma unroll
        for (int c = 0; c < CC; c++) row[3 + c] = fb[(size_t)c * HW];

        unsigned mbits = 0;
        #pragma unroll
        for (int j = 0; j < JJ; j++)
            mbits |= ((unsigned)mask_in[(size_t)j * BHW + bp] & 1u) << j;
        s_bits[tid] = mbits;
    }

    __syncthreads();

    // ---------------- Phase 2: warp w streams joint w ----------------
    const int wrp  = tid >> 5;   // 0..14 == joint id
    const int lane = tid & 31;
    const unsigned bit = 1u << wrp;

    float* dst = out + ((long)wrp * BHW + bp0) * ROW;   // 17920 B contiguous slab

    #pragma unroll 5
    for (int it = 0; it < 35; it++) {                   // 1120 float4 per joint-slab
        int c   = it * 32 + lane;
        int s4  = c * 4;
        int q   = s4 / 35;                              // point 0..127
        int rem = s4 - q * 35;
        int bnd = 35 - rem;                             // elems with idx < bnd belong to q

        float4 v = *(const float4*)(s_pc + s4);
        unsigned b0 = s_bits[q];
        unsigned b1 = (bnd < 4) ? s_bits[q + 1] : b0;   // straddle => q <= 126
        float4 o;
        o.x = (b0 & bit)                    ? v.x : 0.0f;
        o.y = (((bnd > 1) ? b0 : b1) & bit) ? v.y : 0.0f;
        o.z = (((bnd > 2) ? b0 : b1) & bit) ? v.z : 0.0f;
        o.w = (((bnd > 3) ? b0 : b1) & bit) ? v.w : 0.0f;
        *(float4*)(dst + s4) = o;
    }
}

extern "C" void kernel_launch(void* const* d_in, const int* in_sizes, int n_in,
                              void* d_out, int out_size) {
    const float* depth = (const float*)d_in[0];   // pred_depth [B,1,H,W]
    const int*   mask  = (const int*)  d_in[1];   // filter_mask [J,B,H,W] int32
    const float* K     = (const float*)d_in[2];   // [B,3,3]
    const float* M     = (const float*)d_in[3];   // [B,4,4]
    const float* diff  = (const float*)d_in[4];   // [B,12]
    const float* trans = (const float*)d_in[5];   // [B,4,4]
    const float* feat  = (const float*)d_in[6];   // [B,C,H,W]

    get_3d_points_kernel<<<BHW / PTS, THREADS>>>(depth, mask, feat,
                                                 K, M, diff, trans,
                                                 (float*)d_out);
}

// round 4
// speedup vs baseline: 1.2449x; 1.1387x over previous
#include <cuda_runtime.h>

#define BB 4
#define CC 32
#define HH 128
#define WW 240
#define JJ 15
#define JG 5                  // joints per block
#define NG (JJ/JG)            // 3 joint groups
#define HW (HH*WW)            // 30720
#define BHW (BB*HW)           // 122880
#define ROW 35                // 3 + C
#define PTS 128               // points per block
#define NCHUNK ((PTS*ROW)/4)  // 1120 float4 per joint slab

__global__ __launch_bounds__(128, 9)
void get_3d_points_kernel(const float* __restrict__ depth_in,
                          const int*   __restrict__ mask_in,
                          const float* __restrict__ feat_in,
                          const float* __restrict__ K_in,
                          const float* __restrict__ M_in,
                          const float* __restrict__ diff_in,
                          const float* __restrict__ trans_in,
                          float*       __restrict__ out) {
    __shared__ float    s_pc[PTS * ROW];   // 17.9 KB: 128 points x 35 floats
    __shared__ unsigned s_bits[PTS];       // 5-joint mask bits per point

    const int tid = threadIdx.x;
    const int j0  = blockIdx.x * JG;       // this block's first joint (x fastest -> L2 reuse)
    const int bp0 = blockIdx.y * PTS;      // block entirely within one batch (HW%128==0)
    const int b   = bp0 / HW;
    const int bp  = bp0 + tid;

    // ---------------- Phase 1: compute 128 points ----------------
    {
        const int p  = bp - b * HW;
        const int hh = p / WW;
        const int ww = p - hh * WW;

        const float* Kb = K_in + b * 9;
        const float fxi = 1.0f / Kb[0];
        const float fyi = 1.0f / Kb[4];
        const float cx = Kb[2], cy = Kb[5];

        // Minv = [R^T, -R^T t], T = trans * Minv (3x4)
        const float* Mb = M_in + b * 16;
        const float* Tr = trans_in + b * 16;
        float T[12];
        #pragma unroll
        for (int i = 0; i < 3; i++) {
            #pragma unroll
            for (int j = 0; j < 4; j++) {
                float s = (j == 3) ? Tr[i*4+3] : 0.0f;
                #pragma unroll
                for (int k = 0; k < 3; k++) {
                    float minv_kj = (j < 3) ? Mb[j*4+k]
                        : -(Mb[0*4+k]*Mb[0*4+3] + Mb[1*4+k]*Mb[1*4+3] + Mb[2*4+k]*Mb[2*4+3]);
                    s += Tr[i*4+k] * minv_kj;
                }
                T[i*4+j] = s;
            }
        }
        const float* D = diff_in + b * 12;
        float d0 = D[0], d1 = D[1], d2 = D[2], d3 = D[3];
        float d4 = D[4], d5 = D[5], d6 = D[6], d7 = D[7];
        float d8 = D[8], d9 = D[9], d10 = D[10], d11 = D[11];

        float x  = (float)(ww + 71) * 4.0f;     // (w+71)*(1920/480)
        float y  = (float)hh * 8.4375f;         // h*(1080/128)
        float xb = (x - cx) * fxi;
        float yb = (y - cy) * fyi;

        float xd = xb, yd = yb;
        #pragma unroll
        for (int it = 0; it < 5; it++) {
            float r2  = xd*xd + yd*yd;
            float num = 1.0f + ((d7*r2 + d6)*r2 + d5)*r2;
            float den = 1.0f + ((d4*r2 + d1)*r2 + d0)*r2;
            float ic  = num / den;
            float r4  = r2 * r2;
            float dX  = 2.0f*d2*xd*yd + d3*(r2 + 2.0f*xd*xd) + d8*r2 + d9*r4;
            float dY  = d2*(r2 + 2.0f*yd*yd) + 2.0f*d3*xd*yd + d10*r2 + d11*r4;
            xd = (xb - dX) * ic;
            yd = (yb - dY) * ic;
        }

        float dep = depth_in[bp];
        float X4 = xd * dep, Y4 = yd * dep;
        float* row = s_pc + tid * ROW;          // stride 35: conflict-free (gcd(35,32)=1)
        row[0] = T[0]*X4 + T[1]*Y4 + T[2]*dep  + T[3];
        row[1] = T[4]*X4 + T[5]*Y4 + T[6]*dep  + T[7];
        row[2] = T[8]*X4 + T[9]*Y4 + T[10]*dep + T[11];

        const float* fb = feat_in + (size_t)b * (CC * HW) + p;
        #pragma unroll
        for (int c = 0; c < CC; c++) row[3 + c] = fb[(size_t)c * HW];

        // pack this block's 5 joint masks for this point
        unsigned mbits = 0;
        #pragma unroll
        for (int jj = 0; jj < JG; jj++)
            mbits |= ((unsigned)mask_in[(size_t)(j0 + jj) * BHW + bp] & 1u) << jj;
        s_bits[tid] = mbits;
    }

    __syncthreads();

    // ---------------- Phase 2: masked broadcast of 5 joint slabs ----------------
    // chunks outer (v + index math hoisted), joints inner (register reuse)
    float* outg = out + ((long)j0 * BHW + bp0) * ROW;

    #pragma unroll
    for (int i = 0; i < 9; i++) {
        int chunk = i * 128 + tid;              // 0..1151, block-wide coalesced
        if (chunk < NCHUNK) {
            int s4  = chunk * 4;
            int q   = s4 / 35;                  // local point 0..127
            int rem = s4 - q * 35;
            int bnd = 35 - rem;                 // elems with idx < bnd belong to q

            float4 v = *(const float4*)(s_pc + s4);
            unsigned b0 = s_bits[q];
            unsigned b1 = (bnd < 4) ? s_bits[q + 1] : b0;   // straddle => q <= 126
            unsigned uy = (bnd > 1) ? b0 : b1;
            unsigned uz = (bnd > 2) ? b0 : b1;
            unsigned uw = (bnd > 3) ? b0 : b1;

            float* dp = outg + s4;
            #pragma unroll
            for (int jj = 0; jj < JG; jj++) {
                const unsigned bit = 1u << jj;
                float4 o;
                o.x = (b0 & bit) ? v.x : 0.0f;
                o.y = (uy & bit) ? v.y : 0.0f;
                o.z = (uz & bit) ? v.z : 0.0f;
                o.w = (uw & bit) ? v.w : 0.0f;
                __stcs((float4*)dp, o);         // streaming: output never re-read
                dp += (long)BHW * ROW;
            }
        }
    }
}

extern "C" void kernel_launch(void* const* d_in, const int* in_sizes, int n_in,
                              void* d_out, int out_size) {
    const float* depth = (const float*)d_in[0];   // pred_depth [B,1,H,W]
    const int*   mask  = (const int*)  d_in[1];   // filter_mask [J,B,H,W] int32
    const float* K     = (const float*)d_in[2];   // [B,3,3]
    const float* M     = (const float*)d_in[3];   // [B,4,4]
    const float* diff  = (const float*)d_in[4];   // [B,12]
    const float* trans = (const float*)d_in[5];   // [B,4,4]
    const float* feat  = (const float*)d_in[6];   // [B,C,H,W]

    dim3 grid(NG, BHW / PTS);   // (3, 960): joint-groups fastest for L2 reuse
    get_3d_points_kernel<<<grid, 128>>>(depth, mask, feat,
                                        K, M, diff, trans,
                                        (float*)d_out);
}